// round 1
// baseline (speedup 1.0000x reference)
#include <cuda_runtime.h>
#include <cuda_bf16.h>

// Problem constants (shapes are fixed by the dataset).
#define NN 50000   // nodes
#define NR 32      // relations
#define DD 64      // d_in == d_out

// Scratch: hW[n, r, o] = sum_i h[n,i] * W[r,i,o]   (50000*32*64 f32 = 409.6 MB)
__device__ float g_hW[(size_t)NN * NR * DD];

// ---------------------------------------------------------------------------
// Kernel 1: dense precompute hW = h @ W  for every (node, relation) pair.
// Block = 256 threads, tile = 64 nodes x 1 relation x 64 outputs.
// Register blocking 4 nodes x 4 outputs per thread.
// ---------------------------------------------------------------------------
__global__ void __launch_bounds__(256) rgcn_gemm(const float* __restrict__ h,
                                                 const float* __restrict__ W,
                                                 int n_nodes) {
    __shared__ float hs[64 * 65];   // padded stride 65: bank-conflict-free column reads
    __shared__ float Ws[64 * 64];   // W[r][i][o], row i contiguous in o -> float4 reads

    const int r        = blockIdx.y;
    const int nodeBase = blockIdx.x * 64;
    const int tid      = threadIdx.x;

    // Stage tiles: 4096 elements each, 16 per thread, coalesced global reads.
#pragma unroll
    for (int k = 0; k < 16; k++) {
        int idx  = tid + k * 256;
        int node = idx >> 6;
        int i    = idx & 63;
        int gn   = nodeBase + node;
        hs[node * 65 + i] = (gn < n_nodes) ? h[(size_t)gn * DD + i] : 0.0f;
        Ws[idx]           = W[(size_t)r * DD * DD + idx];
    }
    __syncthreads();

    const int to = (tid & 15) * 4;  // output-col group (16 groups of 4)
    const int tn = tid >> 4;        // node group base (16 groups; nodes tn, tn+16, tn+32, tn+48)

    float acc[4][4];
#pragma unroll
    for (int j = 0; j < 4; j++)
#pragma unroll
        for (int q = 0; q < 4; q++) acc[j][q] = 0.0f;

#pragma unroll 8
    for (int i = 0; i < 64; i++) {
        const float4 w4 = *(const float4*)&Ws[i * 64 + to];
        float hv[4];
#pragma unroll
        for (int j = 0; j < 4; j++) hv[j] = hs[(tn + 16 * j) * 65 + i];
#pragma unroll
        for (int j = 0; j < 4; j++) {
            acc[j][0] = fmaf(hv[j], w4.x, acc[j][0]);
            acc[j][1] = fmaf(hv[j], w4.y, acc[j][1]);
            acc[j][2] = fmaf(hv[j], w4.z, acc[j][2]);
            acc[j][3] = fmaf(hv[j], w4.w, acc[j][3]);
        }
    }

#pragma unroll
    for (int j = 0; j < 4; j++) {
        int gn = nodeBase + tn + 16 * j;
        if (gn < n_nodes) {
            float4 v = make_float4(acc[j][0], acc[j][1], acc[j][2], acc[j][3]);
            *(float4*)&g_hW[((size_t)gn * NR + r) * DD + to] = v;
        }
    }
}

// ---------------------------------------------------------------------------
// Kernel 2: per-edge gather of hW[src, rel, :], scale by norm, atomic scatter
// into out[dst, :]. 16 threads per edge, float4 per thread.
// ---------------------------------------------------------------------------
__global__ void __launch_bounds__(256) rgcn_edge(const int* __restrict__ src,
                                                 const int* __restrict__ dst,
                                                 const int* __restrict__ rel,
                                                 const float* __restrict__ norm,
                                                 float* __restrict__ out,
                                                 int n_edges) {
    long long t = (long long)blockIdx.x * 256 + threadIdx.x;
    int e = (int)(t >> 4);
    if (e >= n_edges) return;
    int q = (int)(t & 15);

    int   s  = __ldg(src + e);
    int   d  = __ldg(dst + e);
    int   r  = __ldg(rel + e);
    float nm = __ldg(norm + e);

    float4 v = *(const float4*)&g_hW[((size_t)s * NR + r) * DD + q * 4];

    float* o = out + (size_t)d * DD + q * 4;
    atomicAdd(o + 0, v.x * nm);
    atomicAdd(o + 1, v.y * nm);
    atomicAdd(o + 2, v.z * nm);
    atomicAdd(o + 3, v.w * nm);
}

// ---------------------------------------------------------------------------
// Launcher. Inputs (metadata order): h, W, src, dst, rel_type, norm.
// Output: [n_nodes, 64] float32.
// ---------------------------------------------------------------------------
extern "C" void kernel_launch(void* const* d_in, const int* in_sizes, int n_in,
                              void* d_out, int out_size) {
    const float* h    = (const float*)d_in[0];
    const float* W    = (const float*)d_in[1];
    const int*   src  = (const int*)d_in[2];
    const int*   dst  = (const int*)d_in[3];
    const int*   rel  = (const int*)d_in[4];
    const float* norm = (const float*)d_in[5];
    float*       out  = (float*)d_out;

    const int n_nodes = in_sizes[0] / DD;   // 50000
    const int n_edges = in_sizes[2];        // 1600000

    // out is poisoned to 0xAA by the harness; atomics need zeros.
    cudaMemsetAsync(out, 0, (size_t)out_size * sizeof(float), 0);

    // Phase 1: hW precompute.
    dim3 g1((n_nodes + 63) / 64, NR);
    rgcn_gemm<<<g1, 256>>>(h, W, n_nodes);

    // Phase 2: edge gather + atomic scatter. 16 threads per edge.
    long long total = (long long)n_edges * 16;
    int blocks = (int)((total + 255) / 256);
    rgcn_edge<<<blocks, 256>>>(src, dst, rel, norm, out, n_edges);
}

// round 2
// speedup vs baseline: 1.5499x; 1.5499x over previous
#include <cuda_runtime.h>
#include <cuda_bf16.h>

#define NN 50000   // nodes
#define NR 32      // relations
#define DD 64      // d_in == d_out

// Scratch: hW[n, r, o] = sum_i h[n,i] * W[r,i,o]   (50000*32*64 f32 = 409.6 MB)
__device__ float g_hW[(size_t)NN * NR * DD];

// packed f32x2 helpers ------------------------------------------------------
__device__ __forceinline__ unsigned long long dup_f32x2(float v) {
    unsigned long long r;
    asm("mov.b64 %0, {%1, %1};" : "=l"(r) : "r"(__float_as_uint(v)));
    return r;
}
__device__ __forceinline__ void fma_f32x2(unsigned long long& acc,
                                          unsigned long long a,
                                          unsigned long long b) {
    asm("fma.rn.f32x2 %0, %1, %2, %0;" : "+l"(acc) : "l"(a), "l"(b));
}

// ---------------------------------------------------------------------------
// Kernel 1: hW = h @ W for every (node, relation).
// Tile: 128 nodes x 64 outputs x (K=64), one relation per block.y.
// 256 threads; each thread: 8 nodes x 4 outputs, node-paired f32x2 math.
// ---------------------------------------------------------------------------
#define HS_STRIDE 132   // i-major h tile stride (pad; 528B = 16B multiple)

__global__ void __launch_bounds__(256) rgcn_gemm(const float* __restrict__ h,
                                                 const float* __restrict__ W,
                                                 int n_nodes) {
    __shared__ float Ws[64 * 64];            // W[r][i][o], o contiguous
    __shared__ float hs_t[64 * HS_STRIDE];   // h tile, i-major: hs_t[i][node]

    const int r        = blockIdx.y;
    const int nodeBase = blockIdx.x * 128;
    const int tid      = threadIdx.x;

    // Stage W: 4096 floats, coalesced.
#pragma unroll
    for (int k = 0; k < 16; k++) {
        int idx = tid + k * 256;
        Ws[idx] = W[(size_t)r * DD * DD + idx];
    }
    // Stage h transposed: 128 nodes x 64 i = 8192 floats. Coalesced global
    // read; transposed smem store (4-way bank conflict, one-time).
#pragma unroll
    for (int k = 0; k < 32; k++) {
        int idx  = tid + k * 256;
        int node = idx >> 6;
        int i    = idx & 63;
        int gn   = nodeBase + node;
        hs_t[i * HS_STRIDE + node] = (gn < n_nodes) ? h[(size_t)gn * DD + i] : 0.0f;
    }
    __syncthreads();

    const int og = (tid & 15) * 4;   // output cols og..og+3
    const int ng = (tid >> 4) * 8;   // node rows ng..ng+7 (4 packed pairs)

    unsigned long long acc[4][4];    // [output o][node-pair np]
#pragma unroll
    for (int o = 0; o < 4; o++)
#pragma unroll
        for (int np = 0; np < 4; np++) acc[o][np] = 0ULL;

#pragma unroll 8
    for (int i = 0; i < 64; i++) {
        const float4 w4 = *(const float4*)&Ws[i * 64 + og];
        unsigned long long wd[4];
        wd[0] = dup_f32x2(w4.x); wd[1] = dup_f32x2(w4.y);
        wd[2] = dup_f32x2(w4.z); wd[3] = dup_f32x2(w4.w);

        // 8 nodes = 4 pre-packed f32x2 pairs, two LDS.128
        const ulonglong2 hA = *(const ulonglong2*)&hs_t[i * HS_STRIDE + ng];
        const ulonglong2 hB = *(const ulonglong2*)&hs_t[i * HS_STRIDE + ng + 4];
        unsigned long long hp[4] = {hA.x, hA.y, hB.x, hB.y};

#pragma unroll
        for (int o = 0; o < 4; o++)
#pragma unroll
            for (int np = 0; np < 4; np++)
                fma_f32x2(acc[o][np], wd[o], hp[np]);
    }

    // Epilogue: unpack pairs -> per-node float4 store to g_hW[node][r][og..]
#pragma unroll
    for (int np = 0; np < 4; np++) {
#pragma unroll
        for (int half = 0; half < 2; half++) {
            int gn = nodeBase + ng + np * 2 + half;
            if (gn < n_nodes) {
                float4 v;
                v.x = ((const float2*)&acc[0][np])[0].x * 0.f; // placeholder avoided below
                float2 p0 = *(float2*)&acc[0][np];
                float2 p1 = *(float2*)&acc[1][np];
                float2 p2 = *(float2*)&acc[2][np];
                float2 p3 = *(float2*)&acc[3][np];
                v.x = half ? p0.y : p0.x;
                v.y = half ? p1.y : p1.x;
                v.z = half ? p2.y : p2.x;
                v.w = half ? p3.y : p3.x;
                *(float4*)&g_hW[((size_t)gn * NR + r) * DD + og] = v;
            }
        }
    }
}

// ---------------------------------------------------------------------------
// Kernel 2: per-edge gather + vectorized red.global.add.v4.f32 scatter.
// 16 threads per edge, one float4 (16B) per thread.
// ---------------------------------------------------------------------------
__global__ void __launch_bounds__(256) rgcn_edge(const int* __restrict__ src,
                                                 const int* __restrict__ dst,
                                                 const int* __restrict__ rel,
                                                 const float* __restrict__ norm,
                                                 float* __restrict__ out,
                                                 int n_edges) {
    long long t = (long long)blockIdx.x * 256 + threadIdx.x;
    int e = (int)(t >> 4);
    if (e >= n_edges) return;
    int q = (int)(t & 15);

    int   s  = __ldg(src + e);
    int   d  = __ldg(dst + e);
    int   r  = __ldg(rel + e);
    float nm = __ldg(norm + e);

    float4 v = *(const float4*)&g_hW[((size_t)s * NR + r) * DD + q * 4];

    float* o = out + (size_t)d * DD + q * 4;
    asm volatile("red.global.add.v4.f32 [%0], {%1, %2, %3, %4};"
                 :: "l"(o), "f"(v.x * nm), "f"(v.y * nm),
                    "f"(v.z * nm), "f"(v.w * nm)
                 : "memory");
}

// ---------------------------------------------------------------------------
extern "C" void kernel_launch(void* const* d_in, const int* in_sizes, int n_in,
                              void* d_out, int out_size) {
    const float* h    = (const float*)d_in[0];
    const float* W    = (const float*)d_in[1];
    const int*   src  = (const int*)d_in[2];
    const int*   dst  = (const int*)d_in[3];
    const int*   rel  = (const int*)d_in[4];
    const float* norm = (const float*)d_in[5];
    float*       out  = (float*)d_out;

    const int n_nodes = in_sizes[0] / DD;   // 50000
    const int n_edges = in_sizes[2];        // 1600000

    cudaMemsetAsync(out, 0, (size_t)out_size * sizeof(float), 0);

    dim3 g1((n_nodes + 127) / 128, NR);
    rgcn_gemm<<<g1, 256>>>(h, W, n_nodes);

    long long total = (long long)n_edges * 16;
    int blocks = (int)((total + 255) / 256);
    rgcn_edge<<<blocks, 256>>>(src, dst, rel, norm, out, n_edges);
}

// round 4
// speedup vs baseline: 2.5340x; 1.6349x over previous
#include <cuda_runtime.h>
#include <cuda_bf16.h>
#include <cstdint>

#define NN 50000   // nodes
#define NR 32      // relations
#define DD 64      // d_in == d_out
#define REL_PER_BLK 4
#define WS_STRIDE 72   // 72 % 32 == 8 -> B-fragment LDS is bank-conflict-free

// Scratch: hW[r][n][o]  (rel-major: GEMM epilogue and edge gather both indexed this way)
__device__ float g_hW[(size_t)NR * NN * DD];

__device__ __forceinline__ uint32_t f2tf32(float f) {
    uint32_t r;
    asm("cvt.rna.tf32.f32 %0, %1;" : "=r"(r) : "f"(f));
    return r;
}

// m16n8k8 tf32 mma (family-common, compiles for compute_103 baseline)
__device__ __forceinline__ void mma_tf32(float* c, const uint32_t* a, const uint32_t* b) {
    asm volatile(
        "mma.sync.aligned.m16n8k8.row.col.f32.tf32.tf32.f32 "
        "{%0,%1,%2,%3}, {%4,%5,%6,%7}, {%8,%9}, {%0,%1,%2,%3};"
        : "+f"(c[0]), "+f"(c[1]), "+f"(c[2]), "+f"(c[3])
        : "r"(a[0]), "r"(a[1]), "r"(a[2]), "r"(a[3]), "r"(b[0]), "r"(b[1]));
}

// ---------------------------------------------------------------------------
// Kernel 1: hW[r][node][o] = h @ W_r via mma.sync tf32.
// Block: 128 threads (4 warps). Tile: 128 nodes x 64 outs x REL_PER_BLK rels.
// Warp tile: 32 nodes x 64 outs = 2 Mtiles x 8 Ntiles, K = 8 steps of 8.
// A fragments (h) live in registers across the whole relation loop.
// ---------------------------------------------------------------------------
__global__ void __launch_bounds__(128) rgcn_gemm_mma(const float* __restrict__ h,
                                                     const float* __restrict__ W,
                                                     int n_nodes) {
    __shared__ uint32_t Ws[64 * WS_STRIDE];   // W_r as tf32 bits, [k][o], stride 72

    const int tid  = threadIdx.x;
    const int wid  = tid >> 5;
    const int lane = tid & 31;
    const int g    = lane >> 2;   // group row 0..7
    const int tg   = lane & 3;    // thread-in-group 0..3

    const int nodeBase = blockIdx.x * 128;
    const int relBase  = blockIdx.y * REL_PER_BLK;
    const int m0       = nodeBase + wid * 32;

    // --- Load A fragments once (h is L2-resident: 12.8MB) ---
    // afr[mt][ks][0..3]: A[g][tg], A[g+8][tg], A[g][tg+4], A[g+8][tg+4]
    uint32_t afr[2][8][4];
#pragma unroll
    for (int mt = 0; mt < 2; mt++) {
        const int r0 = m0 + mt * 16 + g;
        const int r1 = r0 + 8;
        const bool v0 = r0 < n_nodes, v1 = r1 < n_nodes;
#pragma unroll
        for (int ks = 0; ks < 8; ks++) {
            const int k0 = ks * 8 + tg;
            afr[mt][ks][0] = v0 ? f2tf32(__ldg(h + (size_t)r0 * DD + k0))     : 0u;
            afr[mt][ks][1] = v1 ? f2tf32(__ldg(h + (size_t)r1 * DD + k0))     : 0u;
            afr[mt][ks][2] = v0 ? f2tf32(__ldg(h + (size_t)r0 * DD + k0 + 4)) : 0u;
            afr[mt][ks][3] = v1 ? f2tf32(__ldg(h + (size_t)r1 * DD + k0 + 4)) : 0u;
        }
    }

    for (int ri = 0; ri < REL_PER_BLK; ri++) {
        const int r = relBase + ri;

        // --- Stage W_r -> smem as tf32, [k][o] with stride 72 ---
        const float4* Wr = (const float4*)(W + (size_t)r * DD * DD);
#pragma unroll
        for (int j = 0; j < 8; j++) {
            const int idx4 = tid + j * 128;       // 1024 float4 total
            const float4 w4 = __ldg(Wr + idx4);
            const int k  = idx4 >> 4;
            const int o4 = (idx4 & 15) * 4;
            uint32_t* p = &Ws[k * WS_STRIDE + o4];
            p[0] = f2tf32(w4.x); p[1] = f2tf32(w4.y);
            p[2] = f2tf32(w4.z); p[3] = f2tf32(w4.w);
        }
        __syncthreads();

        // --- Compute: acc[mt][nt][4] ---
        float acc[2][8][4];
#pragma unroll
        for (int mt = 0; mt < 2; mt++)
#pragma unroll
            for (int nt = 0; nt < 8; nt++)
#pragma unroll
                for (int q = 0; q < 4; q++) acc[mt][nt][q] = 0.0f;

#pragma unroll
        for (int ks = 0; ks < 8; ks++) {
            // B fragments: b0 = B[k0+tg][n], b1 = B[k0+tg+4][n]; conflict-free
            uint32_t b[8][2];
            const int kA = (ks * 8 + tg) * WS_STRIDE;
            const int kB = (ks * 8 + tg + 4) * WS_STRIDE;
#pragma unroll
            for (int nt = 0; nt < 8; nt++) {
                b[nt][0] = Ws[kA + nt * 8 + g];
                b[nt][1] = Ws[kB + nt * 8 + g];
            }
#pragma unroll
            for (int mt = 0; mt < 2; mt++)
#pragma unroll
                for (int nt = 0; nt < 8; nt++)
                    mma_tf32(acc[mt][nt], afr[mt][ks], b[nt]);
        }

        // --- Epilogue: float2 per (row, ntile); 32B-contiguous per row ---
#pragma unroll
        for (int mt = 0; mt < 2; mt++) {
            const int r0 = m0 + mt * 16 + g;
            const int r1 = r0 + 8;
#pragma unroll
            for (int nt = 0; nt < 8; nt++) {
                const int oc = nt * 8 + 2 * tg;
                if (r0 < n_nodes)
                    *(float2*)&g_hW[((size_t)r * NN + r0) * DD + oc] =
                        make_float2(acc[mt][nt][0], acc[mt][nt][1]);
                if (r1 < n_nodes)
                    *(float2*)&g_hW[((size_t)r * NN + r1) * DD + oc] =
                        make_float2(acc[mt][nt][2], acc[mt][nt][3]);
            }
        }
        __syncthreads();   // before Ws restage
    }
}

// ---------------------------------------------------------------------------
// Kernel 2: per-edge gather + red.global.add.v4.f32 scatter (16 thr/edge).
// ---------------------------------------------------------------------------
__global__ void __launch_bounds__(256) rgcn_edge(const int* __restrict__ src,
                                                 const int* __restrict__ dst,
                                                 const int* __restrict__ rel,
                                                 const float* __restrict__ norm,
                                                 float* __restrict__ out,
                                                 int n_edges) {
    long long t = (long long)blockIdx.x * 256 + threadIdx.x;
    int e = (int)(t >> 4);
    if (e >= n_edges) return;
    int q = (int)(t & 15);

    int   s  = __ldg(src + e);
    int   d  = __ldg(dst + e);
    int   r  = __ldg(rel + e);
    float nm = __ldg(norm + e);

    float4 v = *(const float4*)&g_hW[((size_t)r * NN + s) * DD + q * 4];

    float* o = out + (size_t)d * DD + q * 4;
    asm volatile("red.global.add.v4.f32 [%0], {%1, %2, %3, %4};"
                 :: "l"(o), "f"(v.x * nm), "f"(v.y * nm),
                    "f"(v.z * nm), "f"(v.w * nm)
                 : "memory");
}

// ---------------------------------------------------------------------------
extern "C" void kernel_launch(void* const* d_in, const int* in_sizes, int n_in,
                              void* d_out, int out_size) {
    const float* h    = (const float*)d_in[0];
    const float* W    = (const float*)d_in[1];
    const int*   src  = (const int*)d_in[2];
    const int*   dst  = (const int*)d_in[3];
    const int*   rel  = (const int*)d_in[4];
    const float* norm = (const float*)d_in[5];
    float*       out  = (float*)d_out;

    const int n_nodes = in_sizes[0] / DD;   // 50000
    const int n_edges = in_sizes[2];        // 1600000

    cudaMemsetAsync(out, 0, (size_t)out_size * sizeof(float), 0);

    dim3 g1((n_nodes + 127) / 128, NR / REL_PER_BLK);
    rgcn_gemm_mma<<<g1, 128>>>(h, W, n_nodes);

    long long total = (long long)n_edges * 16;
    int blocks = (int)((total + 255) / 256);
    rgcn_edge<<<blocks, 256>>>(src, dst, rel, norm, out, n_edges);
}

// round 5
// speedup vs baseline: 2.8902x; 1.1406x over previous
#include <cuda_runtime.h>
#include <cuda_bf16.h>
#include <cstdint>

#define NN 50000
#define NR 32
#define DD 64
#define NE_MAX 1600000
#define PADMAX (NR * 128)
#define WS_STRIDE 72   // ≡8 mod 32 -> B-fragment LDS conflict-free
#define ASTR 68        // ≡4 mod 32 -> A-fragment LDS conflict-free (4g+tg bijective)

// Scratch: relation-sorted edge arrays (+ per-bucket 128-row padding, norm=0)
__device__ int   g_srcS[NE_MAX + PADMAX];
__device__ int   g_dstS[NE_MAX + PADMAX];
__device__ float g_normS[NE_MAX + PADMAX];
__device__ int   g_binCount[NR];
__device__ int   g_cursor[NR];
__device__ int   g_tileRel[NE_MAX / 128 + NR + 2];
__device__ int   g_numTiles;

__device__ __forceinline__ uint32_t f2tf32(float f) {
    uint32_t r;
    asm("cvt.rna.tf32.f32 %0, %1;" : "=r"(r) : "f"(f));
    return r;
}
__device__ __forceinline__ void mma_tf32(float* c, const uint32_t* a, const uint32_t* b) {
    asm volatile(
        "mma.sync.aligned.m16n8k8.row.col.f32.tf32.tf32.f32 "
        "{%0,%1,%2,%3}, {%4,%5,%6,%7}, {%8,%9}, {%0,%1,%2,%3};"
        : "+f"(c[0]), "+f"(c[1]), "+f"(c[2]), "+f"(c[3])
        : "r"(a[0]), "r"(a[1]), "r"(a[2]), "r"(a[3]), "r"(b[0]), "r"(b[1]));
}

// ---------------------------------------------------------------------------
// Sort pass 1: per-relation histogram (block-local smem hist, 32 global adds).
// ---------------------------------------------------------------------------
__global__ void k_hist(const int* __restrict__ rel, int n) {
    __shared__ int sh[NR];
    if (threadIdx.x < NR) sh[threadIdx.x] = 0;
    __syncthreads();
    for (int i = blockIdx.x * blockDim.x + threadIdx.x; i < n;
         i += gridDim.x * blockDim.x)
        atomicAdd(&sh[__ldg(rel + i)], 1);
    __syncthreads();
    if (threadIdx.x < NR) atomicAdd(&g_binCount[threadIdx.x], sh[threadIdx.x]);
}

// ---------------------------------------------------------------------------
// Sort pass 2: 128-aligned exclusive prefix; init cursors; fill tile->rel map.
// Launch with exactly 32 threads.
// ---------------------------------------------------------------------------
__global__ void k_prefix() {
    int r = threadIdx.x;
    int cnt = g_binCount[r];
    int tiles = (cnt + 127) >> 7;
    int t = tiles;
#pragma unroll
    for (int d = 1; d < 32; d <<= 1) {
        int v = __shfl_up_sync(0xFFFFFFFFu, t, d);
        if (r >= d) t += v;
    }
    int tileBase = t - tiles;            // exclusive scan
    g_cursor[r] = tileBase * 128;        // element base (128-aligned)
    for (int i = 0; i < tiles; i++) g_tileRel[tileBase + i] = r;
    if (r == 31) g_numTiles = t;
}

// ---------------------------------------------------------------------------
// Sort pass 3: scatter edges into relation buckets (block-aggregated atomics).
// ---------------------------------------------------------------------------
__global__ void __launch_bounds__(256) k_scatter(const int* __restrict__ src,
                                                 const int* __restrict__ dst,
                                                 const int* __restrict__ rel,
                                                 const float* __restrict__ norm,
                                                 int n) {
    __shared__ int sh_cnt[NR], sh_base[NR], sh_pos[NR];
    const int tid = threadIdx.x;
    if (tid < NR) { sh_cnt[tid] = 0; sh_pos[tid] = 0; }
    __syncthreads();
    const int i = blockIdx.x * 256 + tid;
    int r = 0, s = 0, d = 0;
    float nm = 0.0f;
    const bool ok = i < n;
    if (ok) {
        r = __ldg(rel + i); s = __ldg(src + i);
        d = __ldg(dst + i); nm = __ldg(norm + i);
        atomicAdd(&sh_cnt[r], 1);
    }
    __syncthreads();
    if (tid < NR && sh_cnt[tid] > 0)
        sh_base[tid] = atomicAdd(&g_cursor[tid], sh_cnt[tid]);
    __syncthreads();
    if (ok) {
        int pos = sh_base[r] + atomicAdd(&sh_pos[r], 1);
        g_srcS[pos] = s; g_dstS[pos] = d; g_normS[pos] = nm;
    }
}

// ---------------------------------------------------------------------------
// Fused kernel: one 128-edge tile per block (relation fixed per tile).
//   gather h[src] (L2) -> smem -> mma.sync tf32 with W[rel] -> *norm ->
//   red.global.add.v2 into out[dst].
// Dynamic smem: Ws[64*72] | As[128*68] | dst[128] | norm[128]  (~54KB)
// ---------------------------------------------------------------------------
__global__ void __launch_bounds__(128) rgcn_fused(const float* __restrict__ h,
                                                  const float* __restrict__ W,
                                                  float* __restrict__ out) {
    extern __shared__ uint32_t smem[];
    uint32_t* Ws     = smem;                     // 64*72
    uint32_t* As     = smem + 64 * WS_STRIDE;    // 128*68
    int*      s_dst  = (int*)(As + 128 * ASTR);  // 128
    float*    s_norm = (float*)(s_dst + 128);    // 128

    const int tile = blockIdx.x;
    if (tile >= g_numTiles) return;
    const int r    = g_tileRel[tile];
    const int row0 = tile << 7;

    const int tid = threadIdx.x, wid = tid >> 5, lane = tid & 31;
    const int g = lane >> 2, tg = lane & 3;

    s_dst[tid]  = g_dstS[row0 + tid];
    s_norm[tid] = g_normS[row0 + tid];

    // Stage W_r -> tf32 smem [k][o], stride 72
    const float4* Wr = (const float4*)(W + (size_t)r * DD * DD);
#pragma unroll
    for (int j = 0; j < 8; j++) {
        const int idx4 = tid + j * 128;
        const float4 w4 = __ldg(Wr + idx4);
        const int k = idx4 >> 4, o4 = (idx4 & 15) * 4;
        uint32_t* p = &Ws[k * WS_STRIDE + o4];
        p[0] = f2tf32(w4.x); p[1] = f2tf32(w4.y);
        p[2] = f2tf32(w4.z); p[3] = f2tf32(w4.w);
    }

    // Stage A: gather 128 h-rows. 8 threads/row, 32B (full sector) per thread.
    const int arow = tid >> 3, chunk = tid & 7;
#pragma unroll
    for (int p = 0; p < 8; p++) {
        const int row = p * 16 + arow;
        const int s = g_srcS[row0 + row];
        const float4* hp = (const float4*)(h + (size_t)s * DD + chunk * 8);
        const float4 v0 = __ldg(hp), v1 = __ldg(hp + 1);
        uint32_t* q = &As[row * ASTR + chunk * 8];
        q[0] = f2tf32(v0.x); q[1] = f2tf32(v0.y);
        q[2] = f2tf32(v0.z); q[3] = f2tf32(v0.w);
        q[4] = f2tf32(v1.x); q[5] = f2tf32(v1.y);
        q[6] = f2tf32(v1.z); q[7] = f2tf32(v1.w);
    }
    __syncthreads();

    float acc[2][8][4];
#pragma unroll
    for (int mt = 0; mt < 2; mt++)
#pragma unroll
        for (int nt = 0; nt < 8; nt++)
#pragma unroll
            for (int q = 0; q < 4; q++) acc[mt][nt][q] = 0.0f;

    const int wrow = wid * 32;
#pragma unroll
    for (int ks = 0; ks < 8; ks++) {
        const int k0 = ks * 8 + tg;
        uint32_t a[2][4];
#pragma unroll
        for (int mt = 0; mt < 2; mt++) {
            const int r0 = wrow + mt * 16 + g;
            a[mt][0] = As[r0 * ASTR + k0];
            a[mt][1] = As[(r0 + 8) * ASTR + k0];
            a[mt][2] = As[r0 * ASTR + k0 + 4];
            a[mt][3] = As[(r0 + 8) * ASTR + k0 + 4];
        }
        uint32_t b[8][2];
        const int kA = k0 * WS_STRIDE;
        const int kB = kA + 4 * WS_STRIDE;
#pragma unroll
        for (int nt = 0; nt < 8; nt++) {
            b[nt][0] = Ws[kA + nt * 8 + g];
            b[nt][1] = Ws[kB + nt * 8 + g];
        }
#pragma unroll
        for (int mt = 0; mt < 2; mt++)
#pragma unroll
            for (int nt = 0; nt < 8; nt++)
                mma_tf32(acc[mt][nt], a[mt], b[nt]);
    }

    // Epilogue: scale by norm, vectorized reduction into out[dst].
#pragma unroll
    for (int mt = 0; mt < 2; mt++) {
        const int lr0 = wrow + mt * 16 + g, lr1 = lr0 + 8;
        const float n0 = s_norm[lr0], n1 = s_norm[lr1];
        float* o0 = out + (size_t)s_dst[lr0] * DD;
        float* o1 = out + (size_t)s_dst[lr1] * DD;
#pragma unroll
        for (int nt = 0; nt < 8; nt++) {
            const int oc = nt * 8 + 2 * tg;
            asm volatile("red.global.add.v2.f32 [%0], {%1, %2};"
                         :: "l"(o0 + oc), "f"(acc[mt][nt][0] * n0),
                            "f"(acc[mt][nt][1] * n0) : "memory");
            asm volatile("red.global.add.v2.f32 [%0], {%1, %2};"
                         :: "l"(o1 + oc), "f"(acc[mt][nt][2] * n1),
                            "f"(acc[mt][nt][3] * n1) : "memory");
        }
    }
}

// ---------------------------------------------------------------------------
extern "C" void kernel_launch(void* const* d_in, const int* in_sizes, int n_in,
                              void* d_out, int out_size) {
    const float* h    = (const float*)d_in[0];
    const float* W    = (const float*)d_in[1];
    const int*   src  = (const int*)d_in[2];
    const int*   dst  = (const int*)d_in[3];
    const int*   rel  = (const int*)d_in[4];
    const float* norm = (const float*)d_in[5];
    float*       out  = (float*)d_out;

    const int n_edges = in_sizes[2];   // 1600000

    // Zero output + scratch (pads must read as src=0, dst=0, norm=0).
    void *p_src, *p_dst, *p_norm, *p_cnt;
    cudaGetSymbolAddress(&p_src,  g_srcS);
    cudaGetSymbolAddress(&p_dst,  g_dstS);
    cudaGetSymbolAddress(&p_norm, g_normS);
    cudaGetSymbolAddress(&p_cnt,  g_binCount);
    cudaMemsetAsync(out,    0, (size_t)out_size * sizeof(float), 0);
    cudaMemsetAsync(p_src,  0, sizeof(int)   * (NE_MAX + PADMAX), 0);
    cudaMemsetAsync(p_dst,  0, sizeof(int)   * (NE_MAX + PADMAX), 0);
    cudaMemsetAsync(p_norm, 0, sizeof(float) * (NE_MAX + PADMAX), 0);
    cudaMemsetAsync(p_cnt,  0, sizeof(int) * NR, 0);

    // Counting sort by relation.
    k_hist<<<592, 256>>>(rel, n_edges);
    k_prefix<<<1, 32>>>();
    k_scatter<<<(n_edges + 255) / 256, 256>>>(src, dst, rel, norm, n_edges);

    // Fused gather-GEMM-scatter.
    const int smem_bytes = (64 * WS_STRIDE + 128 * ASTR + 128 + 128) * 4;
    static bool attr_set = false;
    if (!attr_set) {
        cudaFuncSetAttribute(rgcn_fused,
                             cudaFuncAttributeMaxDynamicSharedMemorySize,
                             smem_bytes);
        attr_set = true;
    }
    const int max_tiles = n_edges / 128 + NR + 1;
    rgcn_fused<<<max_tiles, 128, smem_bytes>>>(h, W, out);
}